// round 8
// baseline (speedup 1.0000x reference)
#include <cuda_runtime.h>
#include <math.h>

// ----------------------------------------------------------------------------
// UnifiedKAN via uniform-bucket piecewise cubics (no interval search).
// 20 splines x NB=128 buckets over [-1,1]; per bucket a centered-monomial
// cubic fitted at Chebyshev nodes (exact off-knot; knot-straddling buckets
// absorb only the f''' jump -> ~1e-5 error). Main kernel: bucket+center are
// arithmetic; eval = ONE LDS.128 + Horner. This round: front-batched loads,
// weights in registers, 256-thr blocks.
// ----------------------------------------------------------------------------

#define GRID_ 5
#define IN_ 4
#define HID_ 4
#define NSPL 20
#define NB 128                    // uniform buckets over [-1,1]
#define HB (2.0f / NB)            // bucket width
#define RWB ((float)NB / 2.0f)    // 1/HB

__device__ float4 g_buckets[NSPL * NB];  // 40 KB
__device__ float g_w[12];                // [0..7] softmax weights, [8] base

// Reference float32 Cox-de Boor (first 8 basis fns), denominators replaced by
// precomputed reciprocals rc[] (0 when den<=1e-8).
__device__ __forceinline__ float eval_ref_spline(float x, const float* kn /*13*/,
                                                 const float* rc /*33*/,
                                                 const float* cf /*8*/) {
    float b[12];
    #pragma unroll
    for (int j = 0; j < 12; j++)
        b[j] = (x >= kn[j] && x < kn[j + 1]) ? 1.0f : 0.0f;
    if (x == kn[12]) b[11] += 1.0f;
    const int off[4] = {0, 0, 12, 23};
    #pragma unroll
    for (int d = 1; d <= 3; d++) {
        int n = 12 - d;
        const float* r = rc + off[d];
        #pragma unroll
        for (int j = 0; j < 11; j++) {
            if (j >= n) break;
            float t1 = (x - kn[j]) * r[j] * b[j];
            float t2 = (kn[d + 1 + j] - x) * r[j + 1] * b[j + 1];
            b[j] = t1 + t2;  // in-place ascending: b[j+1] still old value
        }
    }
    float s = 0.0f;
    #pragma unroll
    for (int j = 0; j < 8; j++) s += b[j] * cf[j];
    return s;
}

// One block per spline, NB threads = one bucket per thread.
__global__ void kan_setup_kernel(const float* __restrict__ l1_coeffs,
                                 const float* __restrict__ l1_kd,
                                 const float* __restrict__ op_alpha,
                                 const float* __restrict__ gumbel,
                                 const float* __restrict__ l2_coeffs,
                                 const float* __restrict__ l2_kd,
                                 const float* __restrict__ base_offset) {
    __shared__ float s_rc[33];

    int s = blockIdx.x;
    int lane = threadIdx.x;
    const float* kd = (s < 16) ? (l1_kd + s * (GRID_ + 1)) : (l2_kd + (s - 16) * (GRID_ + 1));
    const float* cf = (s < 16) ? (l1_coeffs + s * 8) : (l2_coeffs + (s - 16) * 8);

    float d[GRID_ + 1];
    float dsum = 0.0f;
    #pragma unroll
    for (int k = 0; k < GRID_ + 1; k++) {
        float v = kd[k];
        d[k] = fmaxf(v, 0.0f) + log1pf(expf(-fabsf(v)));  // stable softplus
        dsum += d[k];
    }
    float kn[13];
    kn[0] = kn[1] = kn[2] = kn[3] = -1.0f;
    float cum = 0.0f;
    #pragma unroll
    for (int k = 0; k < 5; k++) {
        cum += d[k] / dsum * 2.0f;
        kn[4 + k] = -1.0f + cum;
    }
    kn[9] = kn[10] = kn[11] = kn[12] = 1.0f;

    if (lane < 33) {
        int t = lane, dd, j;
        if (t < 12)      { dd = 1; j = t; }
        else if (t < 23) { dd = 2; j = t - 12; }
        else             { dd = 3; j = t - 23; }
        float den = kn[dd + j] - kn[j];
        s_rc[t] = (den > 1e-8f) ? 1.0f / den : 0.0f;
    }
    if (s == 0) {
        if (lane >= 40 && lane < 40 + HID_) {
            int h = lane - 40;
            float a0 = op_alpha[h * 2 + 0] + gumbel[h * 2 + 0];
            float a1 = op_alpha[h * 2 + 1] + gumbel[h * 2 + 1];
            float mx = fmaxf(a0, a1);
            float e0 = expf(a0 - mx), e1 = expf(a1 - mx);
            float inv = 1.0f / (e0 + e1);
            g_w[h * 2 + 0] = e0 * inv;
            g_w[h * 2 + 1] = e1 * inv;
        }
        if (lane == 44) g_w[8] = base_offset[0];
    }
    __syncthreads();

    // Fit cubic on bucket at 4 Chebyshev nodes in s = (x - m)/HB.
    const float sn0 = -0.4619397663f, sn1 = -0.1913417162f,
                sn2 =  0.1913417162f, sn3 =  0.4619397663f;
    int b = lane;
    float lo = -1.0f + (float)b * HB;
    float m  = lo + 0.5f * HB;
    float f0 = eval_ref_spline(fmaf(sn0, HB, m), kn, s_rc, cf);
    float f1 = eval_ref_spline(fmaf(sn1, HB, m), kn, s_rc, cf);
    float f2 = eval_ref_spline(fmaf(sn2, HB, m), kn, s_rc, cf);
    float f3 = eval_ref_spline(fmaf(sn3, HB, m), kn, s_rc, cf);

    float c01   = (f1 - f0) * (1.0f / (sn1 - sn0));
    float c12   = (f2 - f1) * (1.0f / (sn2 - sn1));
    float c23   = (f3 - f2) * (1.0f / (sn3 - sn2));
    float c012  = (c12 - c01) * (1.0f / (sn2 - sn0));
    float c123  = (c23 - c12) * (1.0f / (sn3 - sn1));
    float c0123 = (c123 - c012) * (1.0f / (sn3 - sn0));
    float p0 = c0123, p1 = 0.0f, p2 = 0.0f, p3 = 0.0f;
    const float nodes[3] = {sn2, sn1, sn0};
    const float adds[3]  = {c012, c01, f0};
    #pragma unroll
    for (int st = 0; st < 3; st++) {
        float vv = nodes[st];
        float q3 = p2, q2 = p1, q1 = p0;
        float q0 = adds[st] - vv * p0;
        q1 -= vv * p1; q2 -= vv * p2; q3 -= vv * p3;
        p0 = q0; p1 = q1; p2 = q2; p3 = q3;
    }
    float4 c;
    c.x = p0;
    c.y = p1 * RWB;
    c.z = p2 * (RWB * RWB);
    c.w = p3 * (RWB * RWB * RWB);
    g_buckets[s * NB + b] = c;
}

__global__ void __launch_bounds__(256, 5) kan_main_kernel(const float4* __restrict__ x,
                                                          float* __restrict__ out, int n) {
    __shared__ __align__(16) float4 s_coef[NSPL * NB];  // 40 KB
    __shared__ float s_wsh[12];
    for (int k = threadIdx.x; k < NSPL * NB; k += blockDim.x) s_coef[k] = g_buckets[k];
    if (threadIdx.x < 12) s_wsh[threadIdx.x] = g_w[threadIdx.x];
    __syncthreads();

    // Weights live in registers: off the LDS port for the whole loop.
    float w[8];
    #pragma unroll
    for (int k = 0; k < 8; k++) w[k] = s_wsh[k];
    float base = s_wsh[8];

    int stride = gridDim.x * blockDim.x;
    for (int i0 = blockIdx.x * blockDim.x + threadIdx.x; i0 < n; i0 += stride) {
        float4 xv = __ldg(&x[i0]);
        float xi[4] = {xv.x, xv.y, xv.z, xv.w};
        int bi[4];
        float ti[4];
        #pragma unroll
        for (int i = 0; i < 4; i++) {
            float f = fminf(fmaf(xi[i], RWB, RWB), (float)(NB - 1));
            int b = (int)f;
            bi[i] = b;
            ti[i] = xi[i] - fmaf((float)b + 0.5f, HB, -1.0f);
        }

        // Front-batch ALL 16 layer-1 loads (independent; ptxas batches to its
        // register budget -> deep MLP feeding the crossbar).
        float4 c[16];
        #pragma unroll
        for (int h = 0; h < HID_; h++)
            #pragma unroll
            for (int i = 0; i < IN_; i++)
                c[h * 4 + i] = s_coef[(h * IN_ + i) * NB + bi[i]];

        // Consume + layer-2.
        float acc = base;
        #pragma unroll
        for (int h = 0; h < HID_; h++) {
            float sum = 0.0f, prod = 1.0f;
            #pragma unroll
            for (int i = 0; i < IN_; i++) {
                float4 cc = c[h * 4 + i];
                float t = ti[i];
                float v = fmaf(fmaf(fmaf(cc.w, t, cc.z), t, cc.y), t, cc.x);
                sum += v;
                prod *= fminf(fmaxf(v, -5.0f), 5.0f);
            }
            float hid = w[h * 2 + 0] * sum + w[h * 2 + 1] * prod;
            float f = fminf(fmaxf(fmaf(hid, RWB, RWB), 0.0f), (float)(NB - 1));
            int b2 = (int)f;
            float t2 = hid - fmaf((float)b2 + 0.5f, HB, -1.0f);
            float4 c2 = s_coef[(16 + h) * NB + b2];
            float v2 = fmaf(fmaf(fmaf(c2.w, t2, c2.z), t2, c2.y), t2, c2.x);
            bool in_range = (hid >= -1.0f) && (hid <= 1.0f);
            acc += in_range ? v2 : 0.0f;
        }
        out[i0] = acc;
    }
}

extern "C" void kernel_launch(void* const* d_in, const int* in_sizes, int n_in,
                              void* d_out, int out_size) {
    const float* x          = (const float*)d_in[0];
    const float* l1_coeffs  = (const float*)d_in[1];
    const float* l1_kd      = (const float*)d_in[2];
    const float* op_alpha   = (const float*)d_in[3];
    const float* gumbel     = (const float*)d_in[4];
    const float* l2_coeffs  = (const float*)d_in[5];
    const float* l2_kd      = (const float*)d_in[6];
    const float* base_off   = (const float*)d_in[7];
    float* out = (float*)d_out;

    int n = in_sizes[0] / IN_;  // N samples

    kan_setup_kernel<<<NSPL, NB>>>(l1_coeffs, l1_kd, op_alpha, gumbel,
                                   l2_coeffs, l2_kd, base_off);
    // 8 blocks/SM x 148 SMs = 1184 blocks x 256 threads, grid-stride.
    kan_main_kernel<<<1184, 256>>>((const float4*)x, out, n);
}

// round 10
// speedup vs baseline: 1.0977x; 1.0977x over previous
#include <cuda_runtime.h>
#include <math.h>

// ----------------------------------------------------------------------------
// UnifiedKAN via uniform-bucket piecewise cubics (no interval search).
// 20 splines x NB=128 buckets over [-1,1]; per bucket a centered-monomial
// cubic fitted at Chebyshev nodes (exact off-knot). Eval = ONE LDS.128 +
// Horner. This round: x-prefetch + h-group software pipelining to feed the
// (conflicted) smem crossbar, which is the measured 12.3us floor.
// ----------------------------------------------------------------------------

#define GRID_ 5
#define IN_ 4
#define HID_ 4
#define NSPL 20
#define NB 128                    // uniform buckets over [-1,1]
#define HB (2.0f / NB)            // bucket width
#define RWB ((float)NB / 2.0f)    // 1/HB

__device__ float4 g_buckets[NSPL * NB];  // 40 KB
__device__ float g_w[12];                // [0..7] softmax weights, [8] base

// Reference float32 Cox-de Boor (first 8 basis fns), denominators replaced by
// precomputed reciprocals rc[] (0 when den<=1e-8).
__device__ __forceinline__ float eval_ref_spline(float x, const float* kn /*13*/,
                                                 const float* rc /*33*/,
                                                 const float* cf /*8*/) {
    float b[12];
    #pragma unroll
    for (int j = 0; j < 12; j++)
        b[j] = (x >= kn[j] && x < kn[j + 1]) ? 1.0f : 0.0f;
    if (x == kn[12]) b[11] += 1.0f;
    const int off[4] = {0, 0, 12, 23};
    #pragma unroll
    for (int d = 1; d <= 3; d++) {
        int n = 12 - d;
        const float* r = rc + off[d];
        #pragma unroll
        for (int j = 0; j < 11; j++) {
            if (j >= n) break;
            float t1 = (x - kn[j]) * r[j] * b[j];
            float t2 = (kn[d + 1 + j] - x) * r[j + 1] * b[j + 1];
            b[j] = t1 + t2;  // in-place ascending: b[j+1] still old value
        }
    }
    float s = 0.0f;
    #pragma unroll
    for (int j = 0; j < 8; j++) s += b[j] * cf[j];
    return s;
}

// One block per spline, NB threads = one bucket per thread.
__global__ void kan_setup_kernel(const float* __restrict__ l1_coeffs,
                                 const float* __restrict__ l1_kd,
                                 const float* __restrict__ op_alpha,
                                 const float* __restrict__ gumbel,
                                 const float* __restrict__ l2_coeffs,
                                 const float* __restrict__ l2_kd,
                                 const float* __restrict__ base_offset) {
    __shared__ float s_rc[33];

    int s = blockIdx.x;
    int lane = threadIdx.x;
    const float* kd = (s < 16) ? (l1_kd + s * (GRID_ + 1)) : (l2_kd + (s - 16) * (GRID_ + 1));
    const float* cf = (s < 16) ? (l1_coeffs + s * 8) : (l2_coeffs + (s - 16) * 8);

    float d[GRID_ + 1];
    float dsum = 0.0f;
    #pragma unroll
    for (int k = 0; k < GRID_ + 1; k++) {
        float v = kd[k];
        d[k] = fmaxf(v, 0.0f) + log1pf(expf(-fabsf(v)));  // stable softplus
        dsum += d[k];
    }
    float kn[13];
    kn[0] = kn[1] = kn[2] = kn[3] = -1.0f;
    float cum = 0.0f;
    #pragma unroll
    for (int k = 0; k < 5; k++) {
        cum += d[k] / dsum * 2.0f;
        kn[4 + k] = -1.0f + cum;
    }
    kn[9] = kn[10] = kn[11] = kn[12] = 1.0f;

    if (lane < 33) {
        int t = lane, dd, j;
        if (t < 12)      { dd = 1; j = t; }
        else if (t < 23) { dd = 2; j = t - 12; }
        else             { dd = 3; j = t - 23; }
        float den = kn[dd + j] - kn[j];
        s_rc[t] = (den > 1e-8f) ? 1.0f / den : 0.0f;
    }
    if (s == 0) {
        if (lane >= 40 && lane < 40 + HID_) {
            int h = lane - 40;
            float a0 = op_alpha[h * 2 + 0] + gumbel[h * 2 + 0];
            float a1 = op_alpha[h * 2 + 1] + gumbel[h * 2 + 1];
            float mx = fmaxf(a0, a1);
            float e0 = expf(a0 - mx), e1 = expf(a1 - mx);
            float inv = 1.0f / (e0 + e1);
            g_w[h * 2 + 0] = e0 * inv;
            g_w[h * 2 + 1] = e1 * inv;
        }
        if (lane == 44) g_w[8] = base_offset[0];
    }
    __syncthreads();

    // Fit cubic on bucket at 4 Chebyshev nodes in s = (x - m)/HB.
    const float sn0 = -0.4619397663f, sn1 = -0.1913417162f,
                sn2 =  0.1913417162f, sn3 =  0.4619397663f;
    int b = lane;
    float lo = -1.0f + (float)b * HB;
    float m  = lo + 0.5f * HB;
    float f0 = eval_ref_spline(fmaf(sn0, HB, m), kn, s_rc, cf);
    float f1 = eval_ref_spline(fmaf(sn1, HB, m), kn, s_rc, cf);
    float f2 = eval_ref_spline(fmaf(sn2, HB, m), kn, s_rc, cf);
    float f3 = eval_ref_spline(fmaf(sn3, HB, m), kn, s_rc, cf);

    float c01   = (f1 - f0) * (1.0f / (sn1 - sn0));
    float c12   = (f2 - f1) * (1.0f / (sn2 - sn1));
    float c23   = (f3 - f2) * (1.0f / (sn3 - sn2));
    float c012  = (c12 - c01) * (1.0f / (sn2 - sn0));
    float c123  = (c23 - c12) * (1.0f / (sn3 - sn1));
    float c0123 = (c123 - c012) * (1.0f / (sn3 - sn0));
    float p0 = c0123, p1 = 0.0f, p2 = 0.0f, p3 = 0.0f;
    const float nodes[3] = {sn2, sn1, sn0};
    const float adds[3]  = {c012, c01, f0};
    #pragma unroll
    for (int st = 0; st < 3; st++) {
        float vv = nodes[st];
        float q3 = p2, q2 = p1, q1 = p0;
        float q0 = adds[st] - vv * p0;
        q1 -= vv * p1; q2 -= vv * p2; q3 -= vv * p3;
        p0 = q0; p1 = q1; p2 = q2; p3 = q3;
    }
    float4 c;
    c.x = p0;
    c.y = p1 * RWB;
    c.z = p2 * (RWB * RWB);
    c.w = p3 * (RWB * RWB * RWB);
    g_buckets[s * NB + b] = c;
}

__global__ void __launch_bounds__(256) kan_main_kernel(const float4* __restrict__ x,
                                                       float* __restrict__ out, int n) {
    __shared__ __align__(16) float4 s_coef[NSPL * NB];  // 40 KB
    __shared__ float s_wsh[12];
    for (int k = threadIdx.x; k < NSPL * NB; k += blockDim.x) s_coef[k] = g_buckets[k];
    if (threadIdx.x < 12) s_wsh[threadIdx.x] = g_w[threadIdx.x];
    __syncthreads();

    const int stride = gridDim.x * blockDim.x;
    int i = blockIdx.x * blockDim.x + threadIdx.x;
    if (i >= n) return;

    float4 xv = __ldg(&x[i]);

    while (true) {
        // Prefetch next iteration's x BEFORE touching this sample: removes
        // the dependent DRAM latency from the per-iteration critical path.
        int inext = i + stride;
        float4 xnext;
        bool have_next = (inext < n);
        if (have_next) xnext = __ldg(&x[inext]);

        float xi[4] = {xv.x, xv.y, xv.z, xv.w};
        int bi[4];
        float ti[4];
        #pragma unroll
        for (int k2 = 0; k2 < 4; k2++) {
            float f = fminf(fmaf(xi[k2], RWB, RWB), (float)(NB - 1));
            int b = (int)f;
            bi[k2] = b;
            ti[k2] = xi[k2] - fmaf((float)b + 0.5f, HB, -1.0f);
        }

        // Software-pipelined layer-1: load h-group g+1 while consuming g.
        float4 cA[4], cB[4];
        #pragma unroll
        for (int k2 = 0; k2 < 4; k2++) cA[k2] = s_coef[k2 * NB + bi[k2]];

        float acc = s_wsh[8];
        #pragma unroll
        for (int h = 0; h < HID_; h++) {
            // issue next group's loads first (independent of current math)
            if (h + 1 < HID_) {
                #pragma unroll
                for (int k2 = 0; k2 < 4; k2++)
                    cB[k2] = s_coef[((h + 1) * IN_ + k2) * NB + bi[k2]];
            }
            float sum = 0.0f, prod = 1.0f;
            #pragma unroll
            for (int k2 = 0; k2 < 4; k2++) {
                float4 cc = cA[k2];
                float t = ti[k2];
                float v = fmaf(fmaf(fmaf(cc.w, t, cc.z), t, cc.y), t, cc.x);
                sum += v;
                prod *= fminf(fmaxf(v, -5.0f), 5.0f);
            }
            float hid = s_wsh[h * 2 + 0] * sum + s_wsh[h * 2 + 1] * prod;
            float f = fminf(fmaxf(fmaf(hid, RWB, RWB), 0.0f), (float)(NB - 1));
            int b2 = (int)f;
            float t2 = hid - fmaf((float)b2 + 0.5f, HB, -1.0f);
            float4 c2 = s_coef[(16 + h) * NB + b2];
            float v2 = fmaf(fmaf(fmaf(c2.w, t2, c2.z), t2, c2.y), t2, c2.x);
            bool in_range = (hid >= -1.0f) && (hid <= 1.0f);
            acc += in_range ? v2 : 0.0f;
            #pragma unroll
            for (int k2 = 0; k2 < 4; k2++) cA[k2] = cB[k2];
        }
        out[i] = acc;

        if (!have_next) break;
        i = inext;
        xv = xnext;
    }
}

extern "C" void kernel_launch(void* const* d_in, const int* in_sizes, int n_in,
                              void* d_out, int out_size) {
    const float* x          = (const float*)d_in[0];
    const float* l1_coeffs  = (const float*)d_in[1];
    const float* l1_kd      = (const float*)d_in[2];
    const float* op_alpha   = (const float*)d_in[3];
    const float* gumbel     = (const float*)d_in[4];
    const float* l2_coeffs  = (const float*)d_in[5];
    const float* l2_kd      = (const float*)d_in[6];
    const float* base_off   = (const float*)d_in[7];
    float* out = (float*)d_out;

    int n = in_sizes[0] / IN_;  // N samples

    kan_setup_kernel<<<NSPL, NB>>>(l1_coeffs, l1_kd, op_alpha, gumbel,
                                   l2_coeffs, l2_kd, base_off);
    // ~4-5 blocks/SM (smem/regs limited), one persistent wave, grid-stride.
    kan_main_kernel<<<592, 256>>>((const float4*)x, out, n);
}